// round 9
// baseline (speedup 1.0000x reference)
#include <cuda_runtime.h>
#include <cuda_bf16.h>
#include <math.h>

// Problem constants
#define NB   2
#define NS   1024
#define ND   512
#define NH   8
#define NDK  64
#define NDFF 2048
#define NL   4
#define NV   50257
#define NM   (NB*NS)          // 2048 rows

// ---------------- scratch (no allocations allowed) ----------------
__device__ float g_x  [NM*ND];
__device__ float g_h  [NM*ND];
__device__ float g_q  [NM*ND];
__device__ float g_k  [NM*ND];
__device__ float g_v  [NM*ND];
__device__ float g_ao [NM*ND];
__device__ float g_ffh[NM*NDFF];

// ---------------- embed: x = emb[tok] + pos ----------------
__global__ void k_embed(const int* __restrict__ tok,
                        const float* __restrict__ emb,
                        const float* __restrict__ pos,
                        float* __restrict__ x)
{
    int i = blockIdx.x * 256 + threadIdx.x;           // over NM*ND = 1,048,576
    if (i < NM * ND) {
        int row = i >> 9;          // /512
        int d   = i & (ND - 1);
        int s   = row & (NS - 1);
        x[i] = emb[(size_t)tok[row] * ND + d] + pos[(size_t)s * ND + d];
    }
}

// ---------------- layernorm: one block(128) per row of 512 ----------------
__global__ void k_ln(const float* __restrict__ X,
                     const float* __restrict__ gw,
                     const float* __restrict__ bw,
                     float* __restrict__ Y)
{
    __shared__ float rs[4], rss[4];
    int row = blockIdx.x;
    int tid = threadIdx.x;                               // 0..127
    const float4* xv = (const float4*)(X + (size_t)row * ND);
    float4 v = xv[tid];
    float s  = v.x + v.y + v.z + v.w;
    float ss = v.x*v.x + v.y*v.y + v.z*v.z + v.w*v.w;
    #pragma unroll
    for (int o = 16; o; o >>= 1) {
        s  += __shfl_xor_sync(0xffffffffu, s,  o);
        ss += __shfl_xor_sync(0xffffffffu, ss, o);
    }
    if ((tid & 31) == 0) { rs[tid >> 5] = s; rss[tid >> 5] = ss; }
    __syncthreads();
    s  = rs[0]  + rs[1]  + rs[2]  + rs[3];
    ss = rss[0] + rss[1] + rss[2] + rss[3];
    float mean = s * (1.0f / ND);
    float var  = ss * (1.0f / ND) - mean * mean;
    float inv  = rsqrtf(var + 1e-5f);
    float4 gg = ((const float4*)gw)[tid];
    float4 bb = ((const float4*)bw)[tid];
    float4 o;
    o.x = (v.x - mean) * inv * gg.x + bb.x;
    o.y = (v.y - mean) * inv * gg.y + bb.y;
    o.z = (v.z - mean) * inv * gg.z + bb.z;
    o.w = (v.w - mean) * inv * gg.w + bb.w;
    ((float4*)(Y + (size_t)row * ND))[tid] = o;
}

// ---------------- tiled SGEMM: C[M,N] = A[M,K] @ B[N,K]^T + bias ----------------
// modes: 0 = plain, 1 = +residual R (same shape as C), 2 = exact GELU
// k-loop is double-buffered in registers: LDG for tile t+1 is issued before the
// FMA block for tile t, hiding global-load latency under compute.
#define BM 128
#define BN 128
#define BK 8

__device__ __forceinline__ float gelu_exact(float v) {
    return 0.5f * v * (1.0f + erff(v * 0.70710678118654752f));
}

__device__ __forceinline__ void gemm_core(
    const float* __restrict__ A, const float* __restrict__ B,
    const float* __restrict__ bias, const float* __restrict__ R,
    float* __restrict__ C, int N, int K, int m0, int n0, int mode,
    float (&As)[BK][BM], float (&Bs)[BK][BN])
{
    const int tid   = threadIdx.x;          // 256 threads
    const int tx    = tid & 15;
    const int ty    = tid >> 4;
    const int ldRow = tid >> 1;             // 0..127
    const int ldCol = (tid & 1) * 4;        // 0 or 4

    float acc[8][8];
    #pragma unroll
    for (int i = 0; i < 8; i++)
        #pragma unroll
        for (int j = 0; j < 8; j++) acc[i][j] = 0.0f;

    const float* Aptr = A + (size_t)(m0 + ldRow) * K + ldCol;
    const bool bValid = (n0 + ldRow) < N;
    const float* Bptr = B + (size_t)(bValid ? (n0 + ldRow) : 0) * K + ldCol;

    // prime: load tile 0 into registers
    float4 av = *(const float4*)(Aptr);
    float4 bv = make_float4(0.f, 0.f, 0.f, 0.f);
    if (bValid) bv = *(const float4*)(Bptr);

    for (int k0 = 0; k0 < K; k0 += BK) {
        __syncthreads();                     // previous compute done reading smem
        As[ldCol + 0][ldRow] = av.x;
        As[ldCol + 1][ldRow] = av.y;
        As[ldCol + 2][ldRow] = av.z;
        As[ldCol + 3][ldRow] = av.w;
        Bs[ldCol + 0][ldRow] = bv.x;
        Bs[ldCol + 1][ldRow] = bv.y;
        Bs[ldCol + 2][ldRow] = bv.z;
        Bs[ldCol + 3][ldRow] = bv.w;
        __syncthreads();

        // issue next tile's global loads NOW; latency hidden by the FMA block
        if (k0 + BK < K) {
            av = *(const float4*)(Aptr + k0 + BK);
            if (bValid) bv = *(const float4*)(Bptr + k0 + BK);
        }

        #pragma unroll
        for (int kk = 0; kk < BK; kk++) {
            float4 a0 = *(const float4*)&As[kk][ty * 8];
            float4 a1 = *(const float4*)&As[kk][ty * 8 + 4];
            float4 b0 = *(const float4*)&Bs[kk][tx * 8];
            float4 b1 = *(const float4*)&Bs[kk][tx * 8 + 4];
            float ar[8] = {a0.x, a0.y, a0.z, a0.w, a1.x, a1.y, a1.z, a1.w};
            float br[8] = {b0.x, b0.y, b0.z, b0.w, b1.x, b1.y, b1.z, b1.w};
            #pragma unroll
            for (int i = 0; i < 8; i++)
                #pragma unroll
                for (int j = 0; j < 8; j++)
                    acc[i][j] += ar[i] * br[j];
        }
    }

    #pragma unroll
    for (int i = 0; i < 8; i++) {
        int m = m0 + ty * 8 + i;
        #pragma unroll
        for (int j = 0; j < 8; j++) {
            int n = n0 + tx * 8 + j;
            if (n < N) {
                float val = acc[i][j] + bias[n];
                if (mode == 1)      val += R[(size_t)m * N + n];
                else if (mode == 2) val = gelu_exact(val);
                C[(size_t)m * N + n] = val;
            }
        }
    }
}

__global__ void __launch_bounds__(256)
k_gemm(const float* __restrict__ A, const float* __restrict__ B,
       const float* __restrict__ bias, const float* __restrict__ R,
       float* __restrict__ C, int N, int K, int mode)
{
    __shared__ float As[BK][BM];
    __shared__ float Bs[BK][BN];
    gemm_core(A, B, bias, R, C, N, K, blockIdx.y * BM, blockIdx.x * BN, mode, As, Bs);
}

// fused QKV: grid.x = 12 (3 chunks x 4 col-tiles), grid.y = 16
__global__ void __launch_bounds__(256)
k_gemm_qkv(const float* __restrict__ A,
           const float* __restrict__ Wq, const float* __restrict__ Wk,
           const float* __restrict__ Wv,
           const float* __restrict__ bq, const float* __restrict__ bk,
           const float* __restrict__ bv,
           float* __restrict__ q, float* __restrict__ k, float* __restrict__ v)
{
    __shared__ float As[BK][BM];
    __shared__ float Bs[BK][BN];
    int chunk = blockIdx.x >> 2;
    const float* B    = (chunk == 0) ? Wq : ((chunk == 1) ? Wk : Wv);
    const float* bias = (chunk == 0) ? bq : ((chunk == 1) ? bk : bv);
    float* C          = (chunk == 0) ? q  : ((chunk == 1) ? k  : v);
    gemm_core(A, B, bias, nullptr, C, ND, ND,
              blockIdx.y * BM, (blockIdx.x & 3) * BN, 0, As, Bs);
}

// ---------------- attention: TQ=4 queries per block, 64 threads ----------------
// grid: (S/TQ, H, B). Two-pass softmax with K/V tiles staged in smem.
#define TQ 4
#define TK 64

__global__ void __launch_bounds__(64)
k_attn(const float* __restrict__ Q, const float* __restrict__ Kc,
       const float* __restrict__ Vc, float* __restrict__ O)
{
    __shared__ float Ks[TK][65];       // K tile, later reused as V tile
    __shared__ float Qs[TQ][64];
    __shared__ float sc[TQ][NS];
    __shared__ float red2[2];

    const int b  = blockIdx.z;
    const int h  = blockIdx.y;
    const int q0 = blockIdx.x * TQ;
    const int tid = threadIdx.x;       // 0..63

    const size_t base = ((size_t)b * NS) * ND + (size_t)h * NDK;

    #pragma unroll
    for (int qq = 0; qq < TQ; qq++)
        Qs[qq][tid] = Q[base + (size_t)(q0 + qq) * ND + tid];

    const int nk = q0 + TQ;                  // max keys needed
    const int nt = (nk + TK - 1) / TK;       // key tiles
    __syncthreads();

    // ---- pass 1: raw scores ----
    for (int t = 0; t < nt; t++) {
        int kt = t * TK;
        #pragma unroll 8
        for (int r = 0; r < TK; r++)
            Ks[r][tid] = Kc[base + (size_t)(kt + r) * ND + tid];
        __syncthreads();
        {
            float kreg[64];
            #pragma unroll
            for (int d = 0; d < 64; d++) kreg[d] = Ks[tid][d];
            int key = kt + tid;
            #pragma unroll
            for (int qq = 0; qq < TQ; qq++) {
                float s = 0.0f;
                #pragma unroll
                for (int d = 0; d < 64; d++) s += Qs[qq][d] * kreg[d];
                sc[qq][key] = s * 0.125f;          // 1/sqrt(64)
            }
        }
        __syncthreads();
    }

    // ---- softmax per query row ----
    for (int qq = 0; qq < TQ; qq++) {
        const int qlen = q0 + qq + 1;
        float m = -1e30f;
        for (int k2 = tid; k2 < qlen; k2 += 64) m = fmaxf(m, sc[qq][k2]);
        #pragma unroll
        for (int o = 16; o; o >>= 1) m = fmaxf(m, __shfl_xor_sync(0xffffffffu, m, o));
        if ((tid & 31) == 0) red2[tid >> 5] = m;
        __syncthreads();
        m = fmaxf(red2[0], red2[1]);
        __syncthreads();

        float ssum = 0.0f;
        for (int k2 = tid; k2 < qlen; k2 += 64) {
            float e = __expf(sc[qq][k2] - m);
            sc[qq][k2] = e;
            ssum += e;
        }
        #pragma unroll
        for (int o = 16; o; o >>= 1) ssum += __shfl_xor_sync(0xffffffffu, ssum, o);
        if ((tid & 31) == 0) red2[tid >> 5] = ssum;
        __syncthreads();
        float inv = 1.0f / (red2[0] + red2[1]);
        for (int k2 = tid; k2 < qlen; k2 += 64) sc[qq][k2] *= inv;
        for (int k2 = qlen + tid; k2 < nt * TK; k2 += 64) sc[qq][k2] = 0.0f;
        __syncthreads();
    }

    // ---- pass 2: O = P @ V ----
    float oacc[TQ] = {0.f, 0.f, 0.f, 0.f};
    for (int t = 0; t < nt; t++) {
        int kt = t * TK;
        #pragma unroll 8
        for (int r = 0; r < TK; r++)
            Ks[r][tid] = Vc[base + (size_t)(kt + r) * ND + tid];
        __syncthreads();
        #pragma unroll
        for (int qq = 0; qq < TQ; qq++) {
            float acc = 0.0f;
            #pragma unroll
            for (int j = 0; j < TK; j++)
                acc += sc[qq][kt + j] * Ks[j][tid];
            oacc[qq] += acc;
        }
        __syncthreads();
    }
    #pragma unroll
    for (int qq = 0; qq < TQ; qq++)
        O[base + (size_t)(q0 + qq) * ND + tid] = oacc[qq];
}

// ---------------- host side ----------------
extern "C" void kernel_launch(void* const* d_in, const int* in_sizes, int n_in,
                              void* d_out, int out_size)
{
    const int*   tok  = (const int*)  d_in[0];
    const float* emb  = (const float*)d_in[1];
    const float* pos  = (const float*)d_in[2];
    const float* Wq   = (const float*)d_in[3];
    const float* bq   = (const float*)d_in[4];
    const float* Wk   = (const float*)d_in[5];
    const float* bk   = (const float*)d_in[6];
    const float* Wv   = (const float*)d_in[7];
    const float* bv   = (const float*)d_in[8];
    const float* Wo   = (const float*)d_in[9];
    const float* bo   = (const float*)d_in[10];
    const float* ln1g = (const float*)d_in[11];
    const float* ln1b = (const float*)d_in[12];
    const float* W1   = (const float*)d_in[13];
    const float* b1   = (const float*)d_in[14];
    const float* W2   = (const float*)d_in[15];
    const float* b2   = (const float*)d_in[16];
    const float* ln2g = (const float*)d_in[17];
    const float* ln2b = (const float*)d_in[18];
    const float* lnfg = (const float*)d_in[19];
    const float* lnfb = (const float*)d_in[20];
    const float* Wh   = (const float*)d_in[21];
    const float* bh   = (const float*)d_in[22];
    float* out = (float*)d_out;

    float *x, *h, *q, *k, *v, *ao, *ffh;
    cudaGetSymbolAddress((void**)&x,   g_x);
    cudaGetSymbolAddress((void**)&h,   g_h);
    cudaGetSymbolAddress((void**)&q,   g_q);
    cudaGetSymbolAddress((void**)&k,   g_k);
    cudaGetSymbolAddress((void**)&v,   g_v);
    cudaGetSymbolAddress((void**)&ao,  g_ao);
    cudaGetSymbolAddress((void**)&ffh, g_ffh);

    k_embed<<<(NM * ND + 255) / 256, 256>>>(tok, emb, pos, x);

    for (int l = 0; l < NL; l++) {
        const size_t wD  = (size_t)l * ND * ND;     // 512x512 weights
        const size_t wF  = (size_t)l * NDFF * ND;   // FFN weights
        const size_t vD  = (size_t)l * ND;
        const size_t vF  = (size_t)l * NDFF;

        k_ln<<<NM, 128>>>(x, ln1g + vD, ln1b + vD, h);
        k_gemm_qkv<<<dim3(12, NM / BM), 256>>>(h, Wq + wD, Wk + wD, Wv + wD,
                                               bq + vD, bk + vD, bv + vD, q, k, v);
        k_attn<<<dim3(NS / TQ, NH, NB), 64>>>(q, k, v, ao);
        k_gemm<<<dim3(ND / BN, NM / BM), 256>>>(ao, Wo + wD, bo + vD, x, x, ND, ND, 1);

        k_ln<<<NM, 128>>>(x, ln2g + vD, ln2b + vD, h);
        k_gemm<<<dim3(NDFF / BN, NM / BM), 256>>>(h, W1 + wF, b1 + vF, nullptr, ffh,
                                                  NDFF, ND, 2);
        k_gemm<<<dim3(ND / BN, NM / BM), 256>>>(ffh, W2 + wF, b2 + vD, x, x,
                                                ND, NDFF, 1);
    }

    k_ln<<<NM, 128>>>(x, lnfg, lnfb, h);
    k_gemm<<<dim3((NV + BN - 1) / BN, NM / BM), 256>>>(h, Wh, bh, nullptr, out,
                                                       NV, ND, 0);
}

// round 10
// speedup vs baseline: 1.8399x; 1.8399x over previous
#include <cuda_runtime.h>
#include <cuda_bf16.h>
#include <math.h>

// Problem constants
#define NB   2
#define NS   1024
#define ND   512
#define NH   8
#define NDK  64
#define NDFF 2048
#define NL   4
#define NV   50257
#define NM   (NB*NS)          // 2048 rows

typedef __nv_bfloat16 bf16;

// ---------------- scratch (no allocations allowed) ----------------
__device__ float g_x [NM*ND];
__device__ float g_q [NM*ND];
__device__ float g_k [NM*ND];
__device__ float g_v [NM*ND];

// activation bf16 hi/lo planes
__device__ bf16 g_hh [NM*ND],   g_hl [NM*ND];     // LN output
__device__ bf16 g_aoh[NM*ND],   g_aol[NM*ND];     // attention output
__device__ bf16 g_fh [NM*NDFF], g_fl [NM*NDFF];   // gelu(ffn1) output

// weight bf16 hi/lo planes
__device__ bf16 g_Wqh[NL*ND*ND],   g_Wql[NL*ND*ND];
__device__ bf16 g_Wkh[NL*ND*ND],   g_Wkl[NL*ND*ND];
__device__ bf16 g_Wvh[NL*ND*ND],   g_Wvl[NL*ND*ND];
__device__ bf16 g_Woh[NL*ND*ND],   g_Wol[NL*ND*ND];
__device__ bf16 g_W1h[NL*NDFF*ND], g_W1l[NL*NDFF*ND];
__device__ bf16 g_W2h[NL*ND*NDFF], g_W2l[NL*ND*NDFF];
__device__ bf16 g_Whh[NV*ND],      g_Whl[NV*ND];

// ---------------- helpers ----------------
__device__ __forceinline__ void fsplit(float v, bf16& hi, bf16& lo) {
    bf16 h = __float2bfloat16(v);
    hi = h;
    lo = __float2bfloat16(v - __bfloat162float(h));
}

__device__ __forceinline__ unsigned smaddr(const void* p) {
    return (unsigned)__cvta_generic_to_shared(p);
}

__device__ __forceinline__ void ldsm_x4(unsigned& r0, unsigned& r1,
                                        unsigned& r2, unsigned& r3, unsigned addr) {
    asm volatile("ldmatrix.sync.aligned.m8n8.x4.shared.b16 {%0,%1,%2,%3}, [%4];\n"
        : "=r"(r0), "=r"(r1), "=r"(r2), "=r"(r3) : "r"(addr));
}

#define MMA16816(ac, a0,a1,a2,a3, b0,b1)                                     \
    asm volatile("mma.sync.aligned.m16n8k16.row.col.f32.bf16.bf16.f32 "      \
        "{%0,%1,%2,%3}, {%4,%5,%6,%7}, {%8,%9}, {%0,%1,%2,%3};\n"            \
        : "+f"((ac)[0]), "+f"((ac)[1]), "+f"((ac)[2]), "+f"((ac)[3])         \
        : "r"(a0), "r"(a1), "r"(a2), "r"(a3), "r"(b0), "r"(b1))

__device__ __forceinline__ float gelu_exact(float v) {
    return 0.5f * v * (1.0f + erff(v * 0.70710678118654752f));
}

// ---------------- weight split: fp32 -> bf16 hi/lo ----------------
__global__ void k_split(const float* __restrict__ src,
                        bf16* __restrict__ hi, bf16* __restrict__ lo, int n)
{
    int i = blockIdx.x * 256 + threadIdx.x;
    if (i < n) {
        float v = src[i];
        bf16 h, l; fsplit(v, h, l);
        hi[i] = h; lo[i] = l;
    }
}

// ---------------- embed: x = emb[tok] + pos ----------------
__global__ void k_embed(const int* __restrict__ tok,
                        const float* __restrict__ emb,
                        const float* __restrict__ pos,
                        float* __restrict__ x)
{
    int i = blockIdx.x * 256 + threadIdx.x;
    if (i < NM * ND) {
        int row = i >> 9;
        int d   = i & (ND - 1);
        int s   = row & (NS - 1);
        x[i] = emb[(size_t)tok[row] * ND + d] + pos[(size_t)s * ND + d];
    }
}

// ---------------- layernorm -> bf16 hi/lo planes ----------------
__global__ void k_ln(const float* __restrict__ X,
                     const float* __restrict__ gw,
                     const float* __restrict__ bw,
                     bf16* __restrict__ Hhi, bf16* __restrict__ Hlo)
{
    __shared__ float rs[4], rss[4];
    int row = blockIdx.x;
    int tid = threadIdx.x;                               // 0..127
    const float4* xv = (const float4*)(X + (size_t)row * ND);
    float4 v = xv[tid];
    float s  = v.x + v.y + v.z + v.w;
    float ss = v.x*v.x + v.y*v.y + v.z*v.z + v.w*v.w;
    #pragma unroll
    for (int o = 16; o; o >>= 1) {
        s  += __shfl_xor_sync(0xffffffffu, s,  o);
        ss += __shfl_xor_sync(0xffffffffu, ss, o);
    }
    if ((tid & 31) == 0) { rs[tid >> 5] = s; rss[tid >> 5] = ss; }
    __syncthreads();
    s  = rs[0]  + rs[1]  + rs[2]  + rs[3];
    ss = rss[0] + rss[1] + rss[2] + rss[3];
    float mean = s * (1.0f / ND);
    float var  = ss * (1.0f / ND) - mean * mean;
    float inv  = rsqrtf(var + 1e-5f);
    float4 gg = ((const float4*)gw)[tid];
    float4 bb = ((const float4*)bw)[tid];
    float o0 = (v.x - mean) * inv * gg.x + bb.x;
    float o1 = (v.y - mean) * inv * gg.y + bb.y;
    float o2 = (v.z - mean) * inv * gg.z + bb.z;
    float o3 = (v.w - mean) * inv * gg.w + bb.w;
    size_t base = (size_t)row * ND + tid * 4;
    bf16 h, l;
    fsplit(o0, h, l); Hhi[base+0] = h; Hlo[base+0] = l;
    fsplit(o1, h, l); Hhi[base+1] = h; Hlo[base+1] = l;
    fsplit(o2, h, l); Hhi[base+2] = h; Hlo[base+2] = l;
    fsplit(o3, h, l); Hhi[base+3] = h; Hlo[base+3] = l;
}

// ---------------- tensor-core GEMM: C[M,N] = A[M,K] @ B[N,K]^T + bias ----------
// A,B given as bf16 hi/lo planes; accumulate hi*hi + hi*lo + lo*hi in fp32.
// modes: 0 = plain -> Cf, 1 = +residual R -> Cf, 2 = gelu -> (Chi,Clo) planes
#define SROW 40   // padded smem row (bf16 elems): bank-conflict-free for ldmatrix

__device__ __forceinline__ void ld_tile(
    uint4 (&p)[8],
    const bf16* __restrict__ Ahi, const bf16* __restrict__ Alo,
    const bf16* __restrict__ Bhi, const bf16* __restrict__ Blo,
    size_t aoff, size_t boff, bool bval, int k0)
{
    p[0] = *(const uint4*)(Ahi + aoff + k0);
    p[1] = *(const uint4*)(Ahi + aoff + k0 + 8);
    p[2] = *(const uint4*)(Alo + aoff + k0);
    p[3] = *(const uint4*)(Alo + aoff + k0 + 8);
    if (bval) {
        p[4] = *(const uint4*)(Bhi + boff + k0);
        p[5] = *(const uint4*)(Bhi + boff + k0 + 8);
        p[6] = *(const uint4*)(Blo + boff + k0);
        p[7] = *(const uint4*)(Blo + boff + k0 + 8);
    } else {
        uint4 z = make_uint4(0u, 0u, 0u, 0u);
        p[4] = z; p[5] = z; p[6] = z; p[7] = z;
    }
}

__device__ __forceinline__ void gemm_tc_core(
    const bf16* __restrict__ Ahi, const bf16* __restrict__ Alo,
    const bf16* __restrict__ Bhi, const bf16* __restrict__ Blo,
    const float* __restrict__ bias, const float* __restrict__ R,
    float* __restrict__ Cf, bf16* __restrict__ Chi, bf16* __restrict__ Clo,
    int N, int K, int m0, int n0, int mode,
    bf16 (&sAh)[128][SROW], bf16 (&sAl)[128][SROW],
    bf16 (&sBh)[128][SROW], bf16 (&sBl)[128][SROW])
{
    const int tid  = threadIdx.x;        // 256 threads, 8 warps
    const int lane = tid & 31;
    const int w    = tid >> 5;
    const int wm   = w >> 1;             // 0..3  (m: 4 x 32)
    const int wn   = w & 1;              // 0..1  (n: 2 x 64)

    float acc[2][8][4];
    #pragma unroll
    for (int i = 0; i < 2; i++)
        #pragma unroll
        for (int j = 0; j < 8; j++)
            #pragma unroll
            for (int r = 0; r < 4; r++) acc[i][j][r] = 0.0f;

    // global loader mapping: 256 threads -> 128 rows x 2 half-rows of 16 bf16
    const int ldr = tid >> 1;
    const int ldc = (tid & 1) * 16;
    const size_t aoff = (size_t)(m0 + ldr) * K + ldc;
    const bool   bval = (n0 + ldr) < N;
    const size_t boff = (size_t)(bval ? (n0 + ldr) : 0) * K + ldc;

    // ldmatrix source addresses (constant across k-iters; add ks*2 bytes)
    const int arow = wm * 32 + (lane & 7) + ((lane & 8) ? 8 : 0);
    const int acol = (lane & 16) ? 8 : 0;
    unsigned aAh[2], aAl[2];
    #pragma unroll
    for (int mf = 0; mf < 2; mf++) {
        aAh[mf] = smaddr(&sAh[arow + mf * 16][acol]);
        aAl[mf] = smaddr(&sAl[arow + mf * 16][acol]);
    }
    const int brow = wn * 64 + (lane & 7) + ((lane & 16) ? 8 : 0);
    const int bcol = (lane & 8) ? 8 : 0;
    unsigned aBh[4], aBl[4];
    #pragma unroll
    for (int pr = 0; pr < 4; pr++) {
        aBh[pr] = smaddr(&sBh[brow + pr * 16][bcol]);
        aBl[pr] = smaddr(&sBl[brow + pr * 16][bcol]);
    }

    uint4 p[8];
    ld_tile(p, Ahi, Alo, Bhi, Blo, aoff, boff, bval, 0);

    for (int k0 = 0; k0 < K; k0 += 32) {
        __syncthreads();
        *(uint4*)&sAh[ldr][ldc]     = p[0];
        *(uint4*)&sAh[ldr][ldc + 8] = p[1];
        *(uint4*)&sAl[ldr][ldc]     = p[2];
        *(uint4*)&sAl[ldr][ldc + 8] = p[3];
        *(uint4*)&sBh[ldr][ldc]     = p[4];
        *(uint4*)&sBh[ldr][ldc + 8] = p[5];
        *(uint4*)&sBl[ldr][ldc]     = p[6];
        *(uint4*)&sBl[ldr][ldc + 8] = p[7];
        __syncthreads();

        if (k0 + 32 < K)
            ld_tile(p, Ahi, Alo, Bhi, Blo, aoff, boff, bval, k0 + 32);

        #pragma unroll
        for (int ks = 0; ks < 32; ks += 16) {
            unsigned ah[2][4], al[2][4], bh[4][4], bl[4][4];
            #pragma unroll
            for (int mf = 0; mf < 2; mf++) {
                ldsm_x4(ah[mf][0], ah[mf][1], ah[mf][2], ah[mf][3], aAh[mf] + ks * 2);
                ldsm_x4(al[mf][0], al[mf][1], al[mf][2], al[mf][3], aAl[mf] + ks * 2);
            }
            #pragma unroll
            for (int pr = 0; pr < 4; pr++) {
                ldsm_x4(bh[pr][0], bh[pr][1], bh[pr][2], bh[pr][3], aBh[pr] + ks * 2);
                ldsm_x4(bl[pr][0], bl[pr][1], bl[pr][2], bl[pr][3], aBl[pr] + ks * 2);
            }
            #pragma unroll
            for (int mf = 0; mf < 2; mf++) {
                #pragma unroll
                for (int nf = 0; nf < 8; nf++) {
                    const unsigned* Bh = &bh[nf >> 1][(nf & 1) * 2];
                    const unsigned* Bl = &bl[nf >> 1][(nf & 1) * 2];
                    MMA16816(acc[mf][nf], ah[mf][0], ah[mf][1], ah[mf][2], ah[mf][3],
                             Bh[0], Bh[1]);
                    MMA16816(acc[mf][nf], ah[mf][0], ah[mf][1], ah[mf][2], ah[mf][3],
                             Bl[0], Bl[1]);
                    MMA16816(acc[mf][nf], al[mf][0], al[mf][1], al[mf][2], al[mf][3],
                             Bh[0], Bh[1]);
                }
            }
        }
    }

    // epilogue
    #pragma unroll
    for (int mf = 0; mf < 2; mf++) {
        #pragma unroll
        for (int nf = 0; nf < 8; nf++) {
            int mb = m0 + wm * 32 + mf * 16 + (lane >> 2);
            int nb = n0 + wn * 64 + nf * 8 + (lane & 3) * 2;
            #pragma unroll
            for (int h2 = 0; h2 < 2; h2++) {
                int m = mb + h2 * 8;
                #pragma unroll
                for (int c = 0; c < 2; c++) {
                    int n = nb + c;
                    if (n < N) {
                        float val = acc[mf][nf][h2 * 2 + c] + bias[n];
                        size_t idx = (size_t)m * N + n;
                        if (mode == 0) {
                            Cf[idx] = val;
                        } else if (mode == 1) {
                            Cf[idx] = val + R[idx];
                        } else {
                            float g = gelu_exact(val);
                            bf16 hh, ll; fsplit(g, hh, ll);
                            Chi[idx] = hh; Clo[idx] = ll;
                        }
                    }
                }
            }
        }
    }
}

__global__ void __launch_bounds__(256)
k_gemm_tc(const bf16* __restrict__ Ahi, const bf16* __restrict__ Alo,
          const bf16* __restrict__ Bhi, const bf16* __restrict__ Blo,
          const float* __restrict__ bias, const float* __restrict__ R,
          float* __restrict__ Cf, bf16* __restrict__ Chi, bf16* __restrict__ Clo,
          int N, int K, int mode)
{
    __shared__ __align__(16) bf16 sAh[128][SROW], sAl[128][SROW];
    __shared__ __align__(16) bf16 sBh[128][SROW], sBl[128][SROW];
    gemm_tc_core(Ahi, Alo, Bhi, Blo, bias, R, Cf, Chi, Clo,
                 N, K, blockIdx.y * 128, blockIdx.x * 128, mode,
                 sAh, sAl, sBh, sBl);
}

// fused QKV: grid.x = 12 (3 chunks x 4 col-tiles), grid.y = 16
__global__ void __launch_bounds__(256)
k_gemm_qkv_tc(const bf16* __restrict__ Ahi, const bf16* __restrict__ Alo,
              const bf16* __restrict__ Wqh, const bf16* __restrict__ Wql,
              const bf16* __restrict__ Wkh, const bf16* __restrict__ Wkl,
              const bf16* __restrict__ Wvh, const bf16* __restrict__ Wvl,
              const float* __restrict__ bq, const float* __restrict__ bk,
              const float* __restrict__ bv,
              float* __restrict__ q, float* __restrict__ k, float* __restrict__ v)
{
    __shared__ __align__(16) bf16 sAh[128][SROW], sAl[128][SROW];
    __shared__ __align__(16) bf16 sBh[128][SROW], sBl[128][SROW];
    int chunk = blockIdx.x >> 2;
    const bf16 *Bh, *Bl; const float* bias; float* C;
    if (chunk == 0)      { Bh = Wqh; Bl = Wql; bias = bq; C = q; }
    else if (chunk == 1) { Bh = Wkh; Bl = Wkl; bias = bk; C = k; }
    else                 { Bh = Wvh; Bl = Wvl; bias = bv; C = v; }
    gemm_tc_core(Ahi, Alo, Bh, Bl, bias, nullptr, C, nullptr, nullptr,
                 ND, ND, blockIdx.y * 128, (blockIdx.x & 3) * 128, 0,
                 sAh, sAl, sBh, sBl);
}

// ---------------- attention: TQ=4 queries per block, 64 threads ----------------
#define TQ 4
#define TK 64

__global__ void __launch_bounds__(64)
k_attn(const float* __restrict__ Q, const float* __restrict__ Kc,
       const float* __restrict__ Vc,
       bf16* __restrict__ Ohi, bf16* __restrict__ Olo)
{
    __shared__ float Ks[TK][65];
    __shared__ float Qs[TQ][64];
    __shared__ float sc[TQ][NS];
    __shared__ float red2[2];

    const int b  = blockIdx.z;
    const int h  = blockIdx.y;
    const int q0 = blockIdx.x * TQ;
    const int tid = threadIdx.x;       // 0..63

    const size_t base = ((size_t)b * NS) * ND + (size_t)h * NDK;

    #pragma unroll
    for (int qq = 0; qq < TQ; qq++)
        Qs[qq][tid] = Q[base + (size_t)(q0 + qq) * ND + tid];

    const int nk = q0 + TQ;
    const int nt = (nk + TK - 1) / TK;
    __syncthreads();

    // pass 1: raw scores
    for (int t = 0; t < nt; t++) {
        int kt = t * TK;
        #pragma unroll 8
        for (int r = 0; r < TK; r++)
            Ks[r][tid] = Kc[base + (size_t)(kt + r) * ND + tid];
        __syncthreads();
        {
            float kreg[64];
            #pragma unroll
            for (int d = 0; d < 64; d++) kreg[d] = Ks[tid][d];
            int key = kt + tid;
            #pragma unroll
            for (int qq = 0; qq < TQ; qq++) {
                float s = 0.0f;
                #pragma unroll
                for (int d = 0; d < 64; d++) s += Qs[qq][d] * kreg[d];
                sc[qq][key] = s * 0.125f;
            }
        }
        __syncthreads();
    }

    // softmax per query row
    for (int qq = 0; qq < TQ; qq++) {
        const int qlen = q0 + qq + 1;
        float m = -1e30f;
        for (int k2 = tid; k2 < qlen; k2 += 64) m = fmaxf(m, sc[qq][k2]);
        #pragma unroll
        for (int o = 16; o; o >>= 1) m = fmaxf(m, __shfl_xor_sync(0xffffffffu, m, o));
        if ((tid & 31) == 0) red2[tid >> 5] = m;
        __syncthreads();
        m = fmaxf(red2[0], red2[1]);
        __syncthreads();

        float ssum = 0.0f;
        for (int k2 = tid; k2 < qlen; k2 += 64) {
            float e = __expf(sc[qq][k2] - m);
            sc[qq][k2] = e;
            ssum += e;
        }
        #pragma unroll
        for (int o = 16; o; o >>= 1) ssum += __shfl_xor_sync(0xffffffffu, ssum, o);
        if ((tid & 31) == 0) red2[tid >> 5] = ssum;
        __syncthreads();
        float inv = 1.0f / (red2[0] + red2[1]);
        for (int k2 = tid; k2 < qlen; k2 += 64) sc[qq][k2] *= inv;
        for (int k2 = qlen + tid; k2 < nt * TK; k2 += 64) sc[qq][k2] = 0.0f;
        __syncthreads();
    }

    // pass 2: O = P @ V
    float oacc[TQ] = {0.f, 0.f, 0.f, 0.f};
    for (int t = 0; t < nt; t++) {
        int kt = t * TK;
        #pragma unroll 8
        for (int r = 0; r < TK; r++)
            Ks[r][tid] = Vc[base + (size_t)(kt + r) * ND + tid];
        __syncthreads();
        #pragma unroll
        for (int qq = 0; qq < TQ; qq++) {
            float acc = 0.0f;
            #pragma unroll
            for (int j = 0; j < TK; j++)
                acc += sc[qq][kt + j] * Ks[j][tid];
            oacc[qq] += acc;
        }
        __syncthreads();
    }
    #pragma unroll
    for (int qq = 0; qq < TQ; qq++) {
        bf16 hh, ll; fsplit(oacc[qq], hh, ll);
        size_t idx = base + (size_t)(q0 + qq) * ND + tid;
        Ohi[idx] = hh; Olo[idx] = ll;
    }
}

// ---------------- host side ----------------
extern "C" void kernel_launch(void* const* d_in, const int* in_sizes, int n_in,
                              void* d_out, int out_size)
{
    const int*   tok  = (const int*)  d_in[0];
    const float* emb  = (const float*)d_in[1];
    const float* pos  = (const float*)d_in[2];
    const float* Wq   = (const float*)d_in[3];
    const float* bq   = (const float*)d_in[4];
    const float* Wk   = (const float*)d_in[5];
    const float* bk   = (const float*)d_in[6];
    const float* Wv   = (const float*)d_in[7];
    const float* bv   = (const float*)d_in[8];
    const float* Wo   = (const float*)d_in[9];
    const float* bo   = (const float*)d_in[10];
    const float* ln1g = (const float*)d_in[11];
    const float* ln1b = (const float*)d_in[12];
    const float* W1   = (const float*)d_in[13];
    const float* b1   = (const float*)d_in[14];
    const float* W2   = (const float*)d_in[15];
    const float* b2   = (const float*)d_in[16];
    const float* ln2g = (const float*)d_in[17];
    const float* ln2b = (const float*)d_in[18];
    const float* lnfg = (const float*)d_in[19];
    const float* lnfb = (const float*)d_in[20];
    const float* Wh   = (const float*)d_in[21];
    const float* bh   = (const float*)d_in[22];
    float* out = (float*)d_out;

    float *x, *q, *k, *v;
    bf16 *hh, *hl, *aoh, *aol, *fh, *fl;
    bf16 *wqh, *wql, *wkh, *wkl, *wvh, *wvl, *woh, *wol;
    bf16 *w1h, *w1l, *w2h, *w2l, *whh, *whl;
    cudaGetSymbolAddress((void**)&x,   g_x);
    cudaGetSymbolAddress((void**)&q,   g_q);
    cudaGetSymbolAddress((void**)&k,   g_k);
    cudaGetSymbolAddress((void**)&v,   g_v);
    cudaGetSymbolAddress((void**)&hh,  g_hh);
    cudaGetSymbolAddress((void**)&hl,  g_hl);
    cudaGetSymbolAddress((void**)&aoh, g_aoh);
    cudaGetSymbolAddress((void**)&aol, g_aol);
    cudaGetSymbolAddress((void**)&fh,  g_fh);
    cudaGetSymbolAddress((void**)&fl,  g_fl);
    cudaGetSymbolAddress((void**)&wqh, g_Wqh);
    cudaGetSymbolAddress((void**)&wql, g_Wql);
    cudaGetSymbolAddress((void**)&wkh, g_Wkh);
    cudaGetSymbolAddress((void**)&wkl, g_Wkl);
    cudaGetSymbolAddress((void**)&wvh, g_Wvh);
    cudaGetSymbolAddress((void**)&wvl, g_Wvl);
    cudaGetSymbolAddress((void**)&woh, g_Woh);
    cudaGetSymbolAddress((void**)&wol, g_Wol);
    cudaGetSymbolAddress((void**)&w1h, g_W1h);
    cudaGetSymbolAddress((void**)&w1l, g_W1l);
    cudaGetSymbolAddress((void**)&w2h, g_W2h);
    cudaGetSymbolAddress((void**)&w2l, g_W2l);
    cudaGetSymbolAddress((void**)&whh, g_Whh);
    cudaGetSymbolAddress((void**)&whl, g_Whl);

    // weight splits (fp32 -> bf16 hi/lo planes)
    const int nD  = NL * ND * ND;
    const int nF  = NL * NDFF * ND;
    const int nHd = NV * ND;
    k_split<<<(nD  + 255) / 256, 256>>>(Wq, wqh, wql, nD);
    k_split<<<(nD  + 255) / 256, 256>>>(Wk, wkh, wkl, nD);
    k_split<<<(nD  + 255) / 256, 256>>>(Wv, wvh, wvl, nD);
    k_split<<<(nD  + 255) / 256, 256>>>(Wo, woh, wol, nD);
    k_split<<<(nF  + 255) / 256, 256>>>(W1, w1h, w1l, nF);
    k_split<<<(nF  + 255) / 256, 256>>>(W2, w2h, w2l, nF);
    k_split<<<(nHd + 255) / 256, 256>>>(Wh, whh, whl, nHd);

    k_embed<<<(NM * ND + 255) / 256, 256>>>(tok, emb, pos, x);

    for (int l = 0; l < NL; l++) {
        const size_t wD = (size_t)l * ND * ND;
        const size_t wF = (size_t)l * NDFF * ND;
        const size_t vD = (size_t)l * ND;
        const size_t vF = (size_t)l * NDFF;

        k_ln<<<NM, 128>>>(x, ln1g + vD, ln1b + vD, hh, hl);
        k_gemm_qkv_tc<<<dim3(12, NM / 128), 256>>>(
            hh, hl, wqh + wD, wql + wD, wkh + wD, wkl + wD, wvh + wD, wvl + wD,
            bq + vD, bk + vD, bv + vD, q, k, v);
        k_attn<<<dim3(NS / TQ, NH, NB), 64>>>(q, k, v, aoh, aol);
        k_gemm_tc<<<dim3(ND / 128, NM / 128), 256>>>(
            aoh, aol, woh + wD, wol + wD, bo + vD, x, x, nullptr, nullptr,
            ND, ND, 1);

        k_ln<<<NM, 128>>>(x, ln2g + vD, ln2b + vD, hh, hl);
        k_gemm_tc<<<dim3(NDFF / 128, NM / 128), 256>>>(
            hh, hl, w1h + wF, w1l + wF, b1 + vF, nullptr, nullptr, fh, fl,
            NDFF, ND, 2);
        k_gemm_tc<<<dim3(ND / 128, NM / 128), 256>>>(
            fh, fl, w2h + wF, w2l + wF, b2 + vD, x, x, nullptr, nullptr,
            ND, NDFF, 1);
    }

    k_ln<<<NM, 128>>>(x, lnfg, lnfb, hh, hl);
    k_gemm_tc<<<dim3((NV + 127) / 128, NM / 128), 256>>>(
        hh, hl, whh, whl, bh, nullptr, out, nullptr, nullptr,
        NV, ND, 0);
}

// round 16
// speedup vs baseline: 1.9916x; 1.0824x over previous
#include <cuda_runtime.h>
#include <cuda_bf16.h>
#include <math.h>

// Problem constants
#define NB   2
#define NS   1024
#define ND   512
#define NH   8
#define NDK  64
#define NDFF 2048
#define NL   4
#define NV   50257
#define NM   (NB*NS)          // 2048 rows

typedef __nv_bfloat16 bf16;

// ---------------- scratch (no allocations allowed) ----------------
__device__ float g_x  [NM*ND];
__device__ float g_h  [NM*ND];
__device__ float g_q  [NM*ND];
__device__ float g_k  [NM*ND];
__device__ float g_v  [NM*ND];
__device__ float g_ao [NM*ND];
__device__ float g_ffh[NM*NDFF];

// ---------------- helpers ----------------
__device__ __forceinline__ unsigned smaddr(const void* p) {
    return (unsigned)__cvta_generic_to_shared(p);
}

__device__ __forceinline__ void ldsm_x4(unsigned& r0, unsigned& r1,
                                        unsigned& r2, unsigned& r3, unsigned addr) {
    asm volatile("ldmatrix.sync.aligned.m8n8.x4.shared.b16 {%0,%1,%2,%3}, [%4];\n"
        : "=r"(r0), "=r"(r1), "=r"(r2), "=r"(r3) : "r"(addr));
}

#define MMA16816(ac, a0,a1,a2,a3, b0,b1)                                     \
    asm volatile("mma.sync.aligned.m16n8k16.row.col.f32.bf16.bf16.f32 "      \
        "{%0,%1,%2,%3}, {%4,%5,%6,%7}, {%8,%9}, {%0,%1,%2,%3};\n"            \
        : "+f"((ac)[0]), "+f"((ac)[1]), "+f"((ac)[2]), "+f"((ac)[3])         \
        : "r"(a0), "r"(a1), "r"(a2), "r"(a3), "r"(b0), "r"(b1))

__device__ __forceinline__ float gelu_exact(float v) {
    return 0.5f * v * (1.0f + erff(v * 0.70710678118654752f));
}

// ---------------- embed: x = emb[tok] + pos ----------------
__global__ void k_embed(const int* __restrict__ tok,
                        const float* __restrict__ emb,
                        const float* __restrict__ pos,
                        float* __restrict__ x)
{
    int i = blockIdx.x * 256 + threadIdx.x;
    if (i < NM * ND) {
        int row = i >> 9;
        int d   = i & (ND - 1);
        int s   = row & (NS - 1);
        x[i] = emb[(size_t)tok[row] * ND + d] + pos[(size_t)s * ND + d];
    }
}

// ---------------- layernorm: one block(128) per row of 512 ----------------
__global__ void k_ln(const float* __restrict__ X,
                     const float* __restrict__ gw,
                     const float* __restrict__ bw,
                     float* __restrict__ Y)
{
    __shared__ float rs[4], rss[4];
    int row = blockIdx.x;
    int tid = threadIdx.x;                               // 0..127
    const float4* xv = (const float4*)(X + (size_t)row * ND);
    float4 v = xv[tid];
    float s  = v.x + v.y + v.z + v.w;
    float ss = v.x*v.x + v.y*v.y + v.z*v.z + v.w*v.w;
    #pragma unroll
    for (int o = 16; o; o >>= 1) {
        s  += __shfl_xor_sync(0xffffffffu, s,  o);
        ss += __shfl_xor_sync(0xffffffffu, ss, o);
    }
    if ((tid & 31) == 0) { rs[tid >> 5] = s; rss[tid >> 5] = ss; }
    __syncthreads();
    s  = rs[0]  + rs[1]  + rs[2]  + rs[3];
    ss = rss[0] + rss[1] + rss[2] + rss[3];
    float mean = s * (1.0f / ND);
    float var  = ss * (1.0f / ND) - mean * mean;
    float inv  = rsqrtf(var + 1e-5f);
    float4 gg = ((const float4*)gw)[tid];
    float4 bb = ((const float4*)bw)[tid];
    float4 o;
    o.x = (v.x - mean) * inv * gg.x + bb.x;
    o.y = (v.y - mean) * inv * gg.y + bb.y;
    o.z = (v.z - mean) * inv * gg.z + bb.z;
    o.w = (v.w - mean) * inv * gg.w + bb.w;
    ((float4*)(Y + (size_t)row * ND))[tid] = o;
}

// ---------------- tensor-core GEMM: C[M,N] = A[M,K] @ B[N,K]^T + bias ----------
// A,B fp32 in global; split to bf16 hi/lo planes on-the-fly at the smem store.
// Accumulate hi*hi + hi*lo + lo*hi in fp32 (error ~2^-17 rel).
// modes: 0 = plain, 1 = +residual R, 2 = exact GELU
#define SROW 40   // padded smem row (bf16 elems): ldmatrix conflict-free

__device__ __forceinline__ void ld_tile(
    uint4 (&p)[8], const float* __restrict__ A, const float* __restrict__ B,
    size_t aoff, size_t boff, bool bval, int k0)
{
    p[0] = *(const uint4*)(A + aoff + k0);
    p[1] = *(const uint4*)(A + aoff + k0 + 4);
    p[2] = *(const uint4*)(A + aoff + k0 + 8);
    p[3] = *(const uint4*)(A + aoff + k0 + 12);
    if (bval) {
        p[4] = *(const uint4*)(B + boff + k0);
        p[5] = *(const uint4*)(B + boff + k0 + 4);
        p[6] = *(const uint4*)(B + boff + k0 + 8);
        p[7] = *(const uint4*)(B + boff + k0 + 12);
    } else {
        uint4 z = make_uint4(0u, 0u, 0u, 0u);
        p[4] = z; p[5] = z; p[6] = z; p[7] = z;
    }
}

// 16 fp32 -> 16 bf16 hi + 16 bf16 lo, stored to one smem row segment
__device__ __forceinline__ void split_store(const uint4* p4,
                                            bf16* __restrict__ hrow,
                                            bf16* __restrict__ lrow)
{
    const float* f = (const float*)p4;
    unsigned hi[8], lo[8];
    #pragma unroll
    for (int i = 0; i < 8; i++) {
        float2 v = make_float2(f[2*i], f[2*i+1]);
        __nv_bfloat162 h = __float22bfloat162_rn(v);
        float2 hf = __bfloat1622float2(h);
        __nv_bfloat162 l = __float22bfloat162_rn(make_float2(v.x - hf.x, v.y - hf.y));
        hi[i] = *(const unsigned*)&h;
        lo[i] = *(const unsigned*)&l;
    }
    *(uint4*)hrow       = make_uint4(hi[0], hi[1], hi[2], hi[3]);
    *(uint4*)(hrow + 8) = make_uint4(hi[4], hi[5], hi[6], hi[7]);
    *(uint4*)lrow       = make_uint4(lo[0], lo[1], lo[2], lo[3]);
    *(uint4*)(lrow + 8) = make_uint4(lo[4], lo[5], lo[6], lo[7]);
}

__device__ __forceinline__ void gemm_tc_core(
    const float* __restrict__ A, const float* __restrict__ B,
    const float* __restrict__ bias, const float* __restrict__ R,
    float* __restrict__ C,
    int N, int K, int m0, int n0, int mode,
    bf16 (&sAh)[128][SROW], bf16 (&sAl)[128][SROW],
    bf16 (&sBh)[128][SROW], bf16 (&sBl)[128][SROW])
{
    const int tid  = threadIdx.x;        // 256 threads, 8 warps
    const int lane = tid & 31;
    const int w    = tid >> 5;
    const int wm   = w >> 1;             // 0..3  (m: 4 x 32)
    const int wn   = w & 1;              // 0..1  (n: 2 x 64)

    float acc[2][8][4];
    #pragma unroll
    for (int i = 0; i < 2; i++)
        #pragma unroll
        for (int j = 0; j < 8; j++)
            #pragma unroll
            for (int r = 0; r < 4; r++) acc[i][j][r] = 0.0f;

    // global loader mapping: 256 threads -> 128 rows x 2 half-rows of 16 fp32
    const int ldr = tid >> 1;
    const int ldc = (tid & 1) * 16;
    const size_t aoff = (size_t)(m0 + ldr) * K + ldc;
    const bool   bval = (n0 + ldr) < N;
    const size_t boff = (size_t)(bval ? (n0 + ldr) : 0) * K + ldc;

    // ldmatrix source addresses (constant across k-iters; add ks*2 bytes)
    const int arow = wm * 32 + (lane & 7) + ((lane & 8) ? 8 : 0);
    const int acol = (lane & 16) ? 8 : 0;
    unsigned aAh[2], aAl[2];
    #pragma unroll
    for (int mf = 0; mf < 2; mf++) {
        aAh[mf] = smaddr(&sAh[arow + mf * 16][acol]);
        aAl[mf] = smaddr(&sAl[arow + mf * 16][acol]);
    }
    const int brow = wn * 64 + (lane & 7) + ((lane & 16) ? 8 : 0);
    const int bcol = (lane & 8) ? 8 : 0;
    unsigned aBh[4], aBl[4];
    #pragma unroll
    for (int pr = 0; pr < 4; pr++) {
        aBh[pr] = smaddr(&sBh[brow + pr * 16][bcol]);
        aBl[pr] = smaddr(&sBl[brow + pr * 16][bcol]);
    }

    uint4 p[8];
    ld_tile(p, A, B, aoff, boff, bval, 0);

    for (int k0 = 0; k0 < K; k0 += 32) {
        __syncthreads();
        split_store(&p[0], &sAh[ldr][ldc], &sAl[ldr][ldc]);
        split_store(&p[4], &sBh[ldr][ldc], &sBl[ldr][ldc]);
        __syncthreads();

        if (k0 + 32 < K)
            ld_tile(p, A, B, aoff, boff, bval, k0 + 32);

        #pragma unroll
        for (int ks = 0; ks < 32; ks += 16) {
            unsigned ah[2][4], al[2][4], bh[4][4], bl[4][4];
            #pragma unroll
            for (int mf = 0; mf < 2; mf++) {
                ldsm_x4(ah[mf][0], ah[mf][1], ah[mf][2], ah[mf][3], aAh[mf] + ks * 2);
                ldsm_x4(al[mf][0], al[mf][1], al[mf][2], al[mf][3], aAl[mf] + ks * 2);
            }
            #pragma unroll
            for (int pr = 0; pr < 4; pr++) {
                ldsm_x4(bh[pr][0], bh[pr][1], bh[pr][2], bh[pr][3], aBh[pr] + ks * 2);
                ldsm_x4(bl[pr][0], bl[pr][1], bl[pr][2], bl[pr][3], aBl[pr] + ks * 2);
            }
            #pragma unroll
            for (int mf = 0; mf < 2; mf++) {
                #pragma unroll
                for (int nf = 0; nf < 8; nf++) {
                    const unsigned* Bh = &bh[nf >> 1][(nf & 1) * 2];
                    const unsigned* Bl = &bl[nf >> 1][(nf & 1) * 2];
                    MMA16816(acc[mf][nf], ah[mf][0], ah[mf][1], ah[mf][2], ah[mf][3],
                             Bh[0], Bh[1]);
                    MMA16816(acc[mf][nf], ah[mf][0], ah[mf][1], ah[mf][2], ah[mf][3],
                             Bl[0], Bl[1]);
                    MMA16816(acc[mf][nf], al[mf][0], al[mf][1], al[mf][2], al[mf][3],
                             Bh[0], Bh[1]);
                }
            }
        }
    }

    // epilogue
    #pragma unroll
    for (int mf = 0; mf < 2; mf++) {
        #pragma unroll
        for (int nf = 0; nf < 8; nf++) {
            int mb = m0 + wm * 32 + mf * 16 + (lane >> 2);
            int nb = n0 + wn * 64 + nf * 8 + (lane & 3) * 2;
            #pragma unroll
            for (int h2 = 0; h2 < 2; h2++) {
                int m = mb + h2 * 8;
                #pragma unroll
                for (int c = 0; c < 2; c++) {
                    int n = nb + c;
                    if (n < N) {
                        float val = acc[mf][nf][h2 * 2 + c] + bias[n];
                        size_t idx = (size_t)m * N + n;
                        if (mode == 1)      val += R[idx];
                        else if (mode == 2) val = gelu_exact(val);
                        C[idx] = val;
                    }
                }
            }
        }
    }
}

__global__ void __launch_bounds__(256)
k_gemm_tc(const float* __restrict__ A, const float* __restrict__ B,
          const float* __restrict__ bias, const float* __restrict__ R,
          float* __restrict__ C, int N, int K, int mode)
{
    __shared__ __align__(16) bf16 sAh[128][SROW], sAl[128][SROW];
    __shared__ __align__(16) bf16 sBh[128][SROW], sBl[128][SROW];
    gemm_tc_core(A, B, bias, R, C, N, K,
                 blockIdx.y * 128, blockIdx.x * 128, mode,
                 sAh, sAl, sBh, sBl);
}

// fused QKV: grid.x = 12 (3 chunks x 4 col-tiles), grid.y = 16
__global__ void __launch_bounds__(256)
k_gemm_qkv_tc(const float* __restrict__ A,
              const float* __restrict__ Wq, const float* __restrict__ Wk,
              const float* __restrict__ Wv,
              const float* __restrict__ bq, const float* __restrict__ bk,
              const float* __restrict__ bv,
              float* __restrict__ q, float* __restrict__ k, float* __restrict__ v)
{
    __shared__ __align__(16) bf16 sAh[128][SROW], sAl[128][SROW];
    __shared__ __align__(16) bf16 sBh[128][SROW], sBl[128][SROW];
    int chunk = blockIdx.x >> 2;
    const float *B, *bias; float* C;
    if (chunk == 0)      { B = Wq; bias = bq; C = q; }
    else if (chunk == 1) { B = Wk; bias = bk; C = k; }
    else                 { B = Wv; bias = bv; C = v; }
    gemm_tc_core(A, B, bias, nullptr, C, ND, ND,
                 blockIdx.y * 128, (blockIdx.x & 3) * 128, 0,
                 sAh, sAl, sBh, sBl);
}

// ---------------- flash attention: TQ=8 queries/block, 64 threads -------------
// Online softmax; K and V tiles stream through ONE smem buffer. thread = dim for
// Q load / V accumulate, thread = key for score compute.
#define TQ 8
#define TK 64
#define TPAD 68   // row pad (floats, mult of 4): aligned float4 + conflict-free

__global__ void __launch_bounds__(64)
k_attn(const float* __restrict__ Q, const float* __restrict__ Kc,
       const float* __restrict__ Vc, float* __restrict__ O)
{
    __shared__ float Ts[TK][TPAD];     // K tile, then V tile
    __shared__ float Qs[TQ][64];
    __shared__ float ps[TQ][TK];
    __shared__ float wmax[2][TQ], wsum[2][TQ];

    const int b   = blockIdx.z;
    const int h   = blockIdx.y;
    const int q0  = blockIdx.x * TQ;
    const int tid = threadIdx.x;       // 0..63
    const int warp = tid >> 5, lane = tid & 31;

    const size_t base = ((size_t)b * NS) * ND + (size_t)h * NDK;

    #pragma unroll
    for (int qq = 0; qq < TQ; qq++)
        Qs[qq][tid] = Q[base + (size_t)(q0 + qq) * ND + tid];

    float m[TQ], l[TQ], oacc[TQ];
    #pragma unroll
    for (int qq = 0; qq < TQ; qq++) { m[qq] = -1e30f; l[qq] = 0.f; oacc[qq] = 0.f; }

    const int nt = (q0 + TQ + TK - 1) / TK;

    for (int t = 0; t < nt; t++) {
        const int kt = t * TK;
        __syncthreads();                               // Ts free (prev V consumed)
        #pragma unroll 8
        for (int r = 0; r < TK; r++)
            Ts[r][tid] = Kc[base + (size_t)(kt + r) * ND + tid];
        __syncthreads();

        // capture this thread's K row into registers (vectorized, conflict-free)
        float4 kv[16];
        #pragma unroll
        for (int i = 0; i < 16; i++) kv[i] = *(const float4*)&Ts[tid][4 * i];
        __syncthreads();                               // all captured; Ts reusable

        // stream V tile into Ts (LDGs overlap the score math below)
        #pragma unroll 8
        for (int r = 0; r < TK; r++)
            Ts[r][tid] = Vc[base + (size_t)(kt + r) * ND + tid];

        // scores: thread = key (kt+tid)
        const int key = kt + tid;
        float sreg[TQ];
        #pragma unroll
        for (int qq = 0; qq < TQ; qq++) {
            float s = 0.f;
            #pragma unroll
            for (int i = 0; i < 16; i++) {
                float4 qv = *(const float4*)&Qs[qq][4 * i];
                s += qv.x * kv[i].x + qv.y * kv[i].y + qv.z * kv[i].z + qv.w * kv[i].w;
            }
            sreg[qq] = (key <= q0 + qq) ? s * 0.125f : -1e30f;
        }

        // tile max per query
        #pragma unroll
        for (int qq = 0; qq < TQ; qq++) {
            float v = sreg[qq];
            #pragma unroll
            for (int o = 16; o; o >>= 1) v = fmaxf(v, __shfl_xor_sync(0xffffffffu, v, o));
            if (lane == 0) wmax[warp][qq] = v;
        }
        __syncthreads();

        float scale[TQ], pv[TQ];
        #pragma unroll
        for (int qq = 0; qq < TQ; qq++) {
            float mt = fmaxf(wmax[0][qq], wmax[1][qq]);
            float mn = fmaxf(m[qq], mt);
            float p  = __expf(sreg[qq] - mn);
            scale[qq] = __expf(m[qq] - mn);
            m[qq] = mn;
            ps[qq][tid] = p;
            pv[qq] = p;
        }
        #pragma unroll
        for (int qq = 0; qq < TQ; qq++) {
            float v = pv[qq];
            #pragma unroll
            for (int o = 16; o; o >>= 1) v += __shfl_xor_sync(0xffffffffu, v, o);
            if (lane == 0) wsum[warp][qq] = v;
        }
        __syncthreads();                               // ps + V visible, wsum ready

        #pragma unroll
        for (int qq = 0; qq < TQ; qq++) {
            l[qq] = l[qq] * scale[qq] + wsum[0][qq] + wsum[1][qq];
            oacc[qq] *= scale[qq];
        }

        // accumulate O: thread = dim
        for (int j = 0; j < TK; j += 4) {
            float v0 = Ts[j][tid], v1 = Ts[j + 1][tid];
            float v2 = Ts[j + 2][tid], v3 = Ts[j + 3][tid];
            #pragma unroll
            for (int qq = 0; qq < TQ; qq++) {
                float4 pp = *(const float4*)&ps[qq][j];
                oacc[qq] += pp.x * v0 + pp.y * v1 + pp.z * v2 + pp.w * v3;
            }
        }
    }

    #pragma unroll
    for (int qq = 0; qq < TQ; qq++)
        O[base + (size_t)(q0 + qq) * ND + tid] = oacc[qq] / l[qq];
}

// ---------------- host side ----------------
extern "C" void kernel_launch(void* const* d_in, const int* in_sizes, int n_in,
                              void* d_out, int out_size)
{
    const int*   tok  = (const int*)  d_in[0];
    const float* emb  = (const float*)d_in[1];
    const float* pos  = (const float*)d_in[2];
    const float* Wq   = (const float*)d_in[3];
    const float* bq   = (const float*)d_in[4];
    const float* Wk   = (const float*)d_in[5];
    const float* bk   = (const float*)d_in[6];
    const float* Wv   = (const float*)d_in[7];
    const float* bv   = (const float*)d_in[8];
    const float* Wo   = (const float*)d_in[9];
    const float* bo   = (const float*)d_in[10];
    const float* ln1g = (const float*)d_in[11];
    const float* ln1b = (const float*)d_in[12];
    const float* W1   = (const float*)d_in[13];
    const float* b1   = (const float*)d_in[14];
    const float* W2   = (const float*)d_in[15];
    const float* b2   = (const float*)d_in[16];
    const float* ln2g = (const float*)d_in[17];
    const float* ln2b = (const float*)d_in[18];
    const float* lnfg = (const float*)d_in[19];
    const float* lnfb = (const float*)d_in[20];
    const float* Wh   = (const float*)d_in[21];
    const float* bh   = (const float*)d_in[22];
    float* out = (float*)d_out;

    float *x, *h, *q, *k, *v, *ao, *ffh;
    cudaGetSymbolAddress((void**)&x,   g_x);
    cudaGetSymbolAddress((void**)&h,   g_h);
    cudaGetSymbolAddress((void**)&q,   g_q);
    cudaGetSymbolAddress((void**)&k,   g_k);
    cudaGetSymbolAddress((void**)&v,   g_v);
    cudaGetSymbolAddress((void**)&ao,  g_ao);
    cudaGetSymbolAddress((void**)&ffh, g_ffh);

    k_embed<<<(NM * ND + 255) / 256, 256>>>(tok, emb, pos, x);

    for (int l = 0; l < NL; l++) {
        const size_t wD = (size_t)l * ND * ND;
        const size_t wF = (size_t)l * NDFF * ND;
        const size_t vD = (size_t)l * ND;
        const size_t vF = (size_t)l * NDFF;

        k_ln<<<NM, 128>>>(x, ln1g + vD, ln1b + vD, h);
        k_gemm_qkv_tc<<<dim3(12, NM / 128), 256>>>(
            h, Wq + wD, Wk + wD, Wv + wD, bq + vD, bk + vD, bv + vD, q, k, v);
        k_attn<<<dim3(NS / TQ, NH, NB), 64>>>(q, k, v, ao);
        k_gemm_tc<<<dim3(ND / 128, NM / 128), 256>>>(
            ao, Wo + wD, bo + vD, x, x, ND, ND, 1);

        k_ln<<<NM, 128>>>(x, ln2g + vD, ln2b + vD, h);
        k_gemm_tc<<<dim3(NDFF / 128, NM / 128), 256>>>(
            h, W1 + wF, b1 + vF, nullptr, ffh, NDFF, ND, 2);
        k_gemm_tc<<<dim3(ND / 128, NM / 128), 256>>>(
            ffh, W2 + wF, b2 + vD, x, x, ND, NDFF, 1);
    }

    k_ln<<<NM, 128>>>(x, lnfg, lnfb, h);
    k_gemm_tc<<<dim3((NV + 127) / 128, NM / 128), 256>>>(
        h, Wh, bh, nullptr, out, NV, ND, 0);
}